// round 1
// baseline (speedup 1.0000x reference)
#include <cuda_runtime.h>
#include <math.h>

#define QN 4
#define RFN 32
#define NSS 4
#define CNN 18
#define HH 64
#define WW 64
#define HWSZ 4096
#define KNN 4

// Output layout: pos(8), scl(4), scores(4*4096), scales(4*4096), offsets(4*2*4096)
#define OFF_POS 0
#define OFF_SCL 8
#define OFF_SCORES 12
#define OFF_SCALES (12 + 16384)
#define OFF_OFFS (12 + 32768)

// ---------------- device scratch (static, no runtime allocation) ----------------
__device__ float g_scale[QN * RFN * NSS * CNN];   // rstd
__device__ float g_shift[QN * RFN * NSS * CNN];   // -mean*rstd
__device__ float g_ys[QN * NSS * 64 * HWSZ];      // per-ns scale-branch features
__device__ float g_yc[QN * NSS * 64 * HWSZ];      // per-ns score-branch features
__device__ float g_xs[QN * 64 * HWSZ];
__device__ float g_xc[QN * 64 * HWSZ];
__device__ float g_t1[QN * 64 * HWSZ];
__device__ float g_t2[QN * 64 * HWSZ];

// ---------------- 1) per-channel mean / rstd ----------------
__global__ void stats_kernel(const float* __restrict__ corr) {
    int b = blockIdx.x;                // channel (q,rfn,ns,cn)
    int tid = threadIdx.x;
    const float* p = corr + (size_t)b * HWSZ;
    double s = 0.0, ss = 0.0;
    for (int i = tid; i < HWSZ; i += 256) {
        float v = p[i];
        s += v;
        ss += (double)v * v;
    }
    for (int o = 16; o > 0; o >>= 1) {
        s += __shfl_down_sync(0xffffffffu, s, o);
        ss += __shfl_down_sync(0xffffffffu, ss, o);
    }
    __shared__ double ws[8], wss[8];
    if ((tid & 31) == 0) { ws[tid >> 5] = s; wss[tid >> 5] = ss; }
    __syncthreads();
    if (tid == 0) {
        double S = 0.0, SS = 0.0;
        for (int i = 0; i < 8; i++) { S += ws[i]; SS += wss[i]; }
        double m = S / (double)HWSZ;
        double var = SS / (double)HWSZ - m * m;
        double rstd = 1.0 / sqrt(var + 1e-5);
        g_scale[b] = (float)rstd;
        g_shift[b] = (float)(-m * rstd);
    }
}

// ---------------- 2) topk + gather + dual MLP per (q,ns,pixel) ----------------
// grid (16, NS, QN), block 256
__global__ void pixel_kernel(const float* __restrict__ corr,
                             const float* __restrict__ w1s, const float* __restrict__ b1s,
                             const float* __restrict__ w2s, const float* __restrict__ b2s,
                             const float* __restrict__ w1c, const float* __restrict__ b1c,
                             const float* __restrict__ w2c, const float* __restrict__ b2c) {
    extern __shared__ float sm[];
    float* sSc = sm;                 // 576
    float* sSh = sSc + 576;          // 576
    float* sW1s = sSh + 576;         // 72*64 (transposed: [in][out])
    float* sW2s = sW1s + 4608;       // 64*64 ([o][j])
    float* sW1c = sW2s + 4096;       // 12*64 (transposed)
    float* sW2c = sW1c + 768;        // 64*64
    float* sB1s = sW2c + 4096;       // 64
    float* sB2s = sB1s + 64;
    float* sB1c = sB2s + 64;
    float* sB2c = sB1c + 64;
    float* sLvl = sB2c + 64;         // 256*13 (padded, per-thread 12 level accums)

    int tid = threadIdx.x;
    int q = blockIdx.z, ns = blockIdx.y;

    for (int i = tid; i < 576; i += 256) {
        int rf = i / 18, cn = i % 18;
        int ch = ((q * RFN + rf) * NSS + ns) * CNN + cn;
        sSc[i] = g_scale[ch];
        sSh[i] = g_shift[ch];
    }
    for (int i = tid; i < 4608; i += 256) sW1s[i] = w1s[(i & 63) * 72 + (i >> 6)];
    for (int i = tid; i < 4096; i += 256) sW2s[i] = w2s[i];
    for (int i = tid; i < 768;  i += 256) sW1c[i] = w1c[(i & 63) * 12 + (i >> 6)];
    for (int i = tid; i < 4096; i += 256) sW2c[i] = w2c[i];
    if (tid < 64) {
        sB1s[tid] = b1s[tid]; sB2s[tid] = b2s[tid];
        sB1c[tid] = b1c[tid]; sB2c[tid] = b2c[tid];
    }
    __syncthreads();

    int hw = blockIdx.x * 256 + tid;
    int cbase = (q * (RFN * NSS * CNN) + ns * CNN) * HWSZ + hw;

    // ---- phase 1: ref score per rfn + top-4 (stable, strict >) ----
    float v0 = -3.4e38f, v1 = v0, v2 = v0, v3 = v0;
    int i0 = 0, i1 = 0, i2 = 0, i3 = 0;
#pragma unroll 1
    for (int rf = 0; rf < RFN; rf++) {
        const float* cp = corr + cbase + rf * (NSS * CNN) * HWSZ;
        float s = 0.f;
#pragma unroll
        for (int cn = 0; cn < CNN; cn++)
            s += fmaf(cp[cn * HWSZ], sSc[rf * 18 + cn], sSh[rf * 18 + cn]);
        if (s > v0)      { v3=v2;i3=i2; v2=v1;i2=i1; v1=v0;i1=i0; v0=s;i0=rf; }
        else if (s > v1) { v3=v2;i3=i2; v2=v1;i2=i1; v1=s;i1=rf; }
        else if (s > v2) { v3=v2;i3=i2; v2=s;i2=rf; }
        else if (s > v3) { v3=s;i3=rf; }
    }
    unsigned packed = (unsigned)i0 | ((unsigned)i1 << 8) | ((unsigned)i2 << 16) | ((unsigned)i3 << 24);

    // ---- phase 2: gather + 72->64 matvec (scale branch), level sums ----
    float h[64];
#pragma unroll
    for (int j = 0; j < 64; j++) h[j] = sB1s[j];
#pragma unroll
    for (int i = 0; i < 12; i++) sLvl[tid * 13 + i] = 0.f;

#pragma unroll 1
    for (int k = 0; k < KNN; k++) {
        int rf = (packed >> (k * 8)) & 255;
        const float* cp = corr + cbase + rf * (NSS * CNN) * HWSZ;
        int sb = rf * 18;
#pragma unroll
        for (int cn = 0; cn < CNN; cn++) {
            float xn = fmaf(cp[cn * HWSZ], sSc[sb + cn], sSh[sb + cn]);
            sLvl[tid * 13 + k * 3 + cn / 6] += xn;
            const float4* wp = (const float4*)&sW1s[(k * 18 + cn) * 64];
#pragma unroll
            for (int jj = 0; jj < 16; jj++) {
                float4 w = wp[jj];
                h[4*jj+0] = fmaf(xn, w.x, h[4*jj+0]);
                h[4*jj+1] = fmaf(xn, w.y, h[4*jj+1]);
                h[4*jj+2] = fmaf(xn, w.z, h[4*jj+2]);
                h[4*jj+3] = fmaf(xn, w.w, h[4*jj+3]);
            }
        }
    }
#pragma unroll
    for (int j = 0; j < 64; j++) h[j] = fmaxf(h[j], 0.f);

    // ---- phase 3: 64->64, write scale-branch features ----
    int obase = ((q * NSS + ns) * 64) * HWSZ + hw;
#pragma unroll 1
    for (int o = 0; o < 64; o++) {
        float acc = sB2s[o];
        const float4* wp = (const float4*)&sW2s[o * 64];
#pragma unroll
        for (int jj = 0; jj < 16; jj++) {
            float4 w = wp[jj];
            acc = fmaf(h[4*jj+0], w.x, acc);
            acc = fmaf(h[4*jj+1], w.y, acc);
            acc = fmaf(h[4*jj+2], w.z, acc);
            acc = fmaf(h[4*jj+3], w.w, acc);
        }
        g_ys[obase + o * HWSZ] = acc;
    }

    // ---- phase 4: score branch 12->64 ----
#pragma unroll
    for (int j = 0; j < 64; j++) h[j] = sB1c[j];
#pragma unroll 1
    for (int i = 0; i < 12; i++) {
        float xv = sLvl[tid * 13 + i] * (1.0f / 6.0f);
        const float4* wp = (const float4*)&sW1c[i * 64];
#pragma unroll
        for (int jj = 0; jj < 16; jj++) {
            float4 w = wp[jj];
            h[4*jj+0] = fmaf(xv, w.x, h[4*jj+0]);
            h[4*jj+1] = fmaf(xv, w.y, h[4*jj+1]);
            h[4*jj+2] = fmaf(xv, w.z, h[4*jj+2]);
            h[4*jj+3] = fmaf(xv, w.w, h[4*jj+3]);
        }
    }
#pragma unroll
    for (int j = 0; j < 64; j++) h[j] = fmaxf(h[j], 0.f);

    // ---- phase 5: 64->64, write score-branch features ----
#pragma unroll 1
    for (int o = 0; o < 64; o++) {
        float acc = sB2c[o];
        const float4* wp = (const float4*)&sW2c[o * 64];
#pragma unroll
        for (int jj = 0; jj < 16; jj++) {
            float4 w = wp[jj];
            acc = fmaf(h[4*jj+0], w.x, acc);
            acc = fmaf(h[4*jj+1], w.y, acc);
            acc = fmaf(h[4*jj+2], w.z, acc);
            acc = fmaf(h[4*jj+3], w.w, acc);
        }
        g_yc[obase + o * HWSZ] = acc;
    }
}

// ---------------- 3) max over ns ----------------
__global__ void maxns_kernel() {
    int idx = blockIdx.x * 256 + threadIdx.x;   // over QN*64*HWSZ = 2^20
    int q = idx >> 18;
    int within = idx & ((1 << 18) - 1);
    int base = (q << 20) + within;
    float a = g_ys[base];
    float b = g_yc[base];
#pragma unroll
    for (int ns = 1; ns < NSS; ns++) {
        a = fmaxf(a, g_ys[base + (ns << 18)]);
        b = fmaxf(b, g_yc[base + (ns << 18)]);
    }
    g_xs[idx] = a;
    g_xc[idx] = b;
}

// ---------------- 4) conv3x3 SAME, 64 in-channels ----------------
// grid (W/16, H/16, QN*chunks), block 256 (16x16 pixels), CO output channels per block
template <int CO, bool RELU>
__global__ void conv3x3_kernel(const float* __restrict__ in, const float* __restrict__ wgt,
                               const float* __restrict__ bias, float* __restrict__ out,
                               int Cout, int chunks) {
    extern __shared__ float sm[];
    float* tile = sm;                   // [64][18][19] (row padded)
    float* wsm = sm + 64 * 342;         // [ci][tap][CO]

    int tid = threadIdx.x;
    int bz = blockIdx.z;
    int q = bz / chunks;
    int co0 = (bz % chunks) * CO;
    int bx = blockIdx.x * 16, by = blockIdx.y * 16;

    for (int i = tid; i < 64 * 324; i += 256) {
        int ci = i / 324;
        int r = i - ci * 324;
        int yy = r / 18, xx = r - yy * 18;
        int gy = by + yy - 1, gx = bx + xx - 1;
        float v = 0.f;
        if (gy >= 0 && gy < HH && gx >= 0 && gx < WW)
            v = in[(q * 64 + ci) * HWSZ + gy * WW + gx];
        tile[ci * 342 + yy * 19 + xx] = v;
    }
    for (int i = tid; i < 64 * 9 * CO; i += 256) {
        int co = i % CO;
        int tap = (i / CO) % 9;
        int ci = i / (9 * CO);
        int cog = co0 + co;
        wsm[i] = (cog < Cout) ? wgt[((cog) * 64 + ci) * 9 + tap] : 0.f;
    }
    __syncthreads();

    int tx = tid & 15, ty = tid >> 4;
    float acc[CO];
#pragma unroll
    for (int c = 0; c < CO; c++) acc[c] = 0.f;

#pragma unroll 1
    for (int ci = 0; ci < 64; ci++) {
        const float* t = &tile[ci * 342 + ty * 19 + tx];
        float a[9];
        a[0]=t[0];  a[1]=t[1];  a[2]=t[2];
        a[3]=t[19]; a[4]=t[20]; a[5]=t[21];
        a[6]=t[38]; a[7]=t[39]; a[8]=t[40];
        const float* wp = &wsm[ci * 9 * CO];
#pragma unroll
        for (int tap = 0; tap < 9; tap++) {
            float av = a[tap];
            if (CO % 4 == 0) {
                const float4* w4 = (const float4*)&wp[tap * CO];
#pragma unroll
                for (int j = 0; j < CO / 4; j++) {
                    float4 w = w4[j];
                    acc[4*j+0] = fmaf(av, w.x, acc[4*j+0]);
                    acc[4*j+1] = fmaf(av, w.y, acc[4*j+1]);
                    acc[4*j+2] = fmaf(av, w.z, acc[4*j+2]);
                    acc[4*j+3] = fmaf(av, w.w, acc[4*j+3]);
                }
            } else {
#pragma unroll
                for (int co = 0; co < CO; co++)
                    acc[co] = fmaf(av, wp[tap * CO + co], acc[co]);
            }
        }
    }

    int gy = by + ty, gx = bx + tx;
#pragma unroll
    for (int co = 0; co < CO; co++) {
        int cog = co0 + co;
        if (cog < Cout) {
            float v = acc[co] + __ldg(&bias[cog]);
            if (RELU) v = fmaxf(v, 0.f);
            out[((q * Cout + cog) << 12) + (gy << 6) + gx] = v;
        }
    }
}

// ---------------- 5) argmax + pos/scl ----------------
__global__ void finalize_kernel(float* out) {
    __shared__ float sv[256];
    __shared__ int si[256];
    int q = blockIdx.x, tid = threadIdx.x;
    const float* sc = out + OFF_SCORES + q * HWSZ;
    float bv = -3.4e38f;
    int bi = 0;
    for (int i = tid; i < HWSZ; i += 256) {
        float v = sc[i];
        if (v > bv) { bv = v; bi = i; }
    }
    sv[tid] = bv; si[tid] = bi;
    __syncthreads();
    for (int s = 128; s > 0; s >>= 1) {
        if (tid < s) {
            if (sv[tid + s] > sv[tid] || (sv[tid + s] == sv[tid] && si[tid + s] < si[tid])) {
                sv[tid] = sv[tid + s];
                si[tid] = si[tid + s];
            }
        }
        __syncthreads();
    }
    if (tid == 0) {
        int idx = si[0];
        int sy = idx >> 6, sx = idx & 63;
        float offx = out[OFF_OFFS + (q * 2 + 0) * HWSZ + idx];
        float offy = out[OFF_OFFS + (q * 2 + 1) * HWSZ + idx];
        float sclv = out[OFF_SCALES + q * HWSZ + idx];
        out[OFF_POS + q * 2 + 0] = ((float)sx + offx + 0.5f) * 8.0f - 0.5f;
        out[OFF_POS + q * 2 + 1] = ((float)sy + offy + 0.5f) * 8.0f - 0.5f;
        out[OFF_SCL + q] = exp2f(sclv);
    }
}

// ---------------- launch ----------------
extern "C" void kernel_launch(void* const* d_in, const int* in_sizes, int n_in,
                              void* d_out, int out_size) {
    const float* corr = (const float*)d_in[0];
    const float* scale_w1 = (const float*)d_in[1];
    const float* scale_b1 = (const float*)d_in[2];
    const float* scale_w2 = (const float*)d_in[3];
    const float* scale_b2 = (const float*)d_in[4];
    const float* score_w1 = (const float*)d_in[5];
    const float* score_b1 = (const float*)d_in[6];
    const float* score_w2 = (const float*)d_in[7];
    const float* score_b2 = (const float*)d_in[8];
    float* out = (float*)d_out;

    float *xs_p, *xc_p, *t1_p, *t2_p;
    cudaGetSymbolAddress((void**)&xs_p, g_xs);
    cudaGetSymbolAddress((void**)&xc_p, g_xc);
    cudaGetSymbolAddress((void**)&t1_p, g_t1);
    cudaGetSymbolAddress((void**)&t2_p, g_t2);

    const int PIX_SMEM = (576*2 + 4608 + 4096 + 768 + 4096 + 256 + 256*13) * 4;
    const int CONV_SMEM32 = (64*342 + 64*9*32) * 4;
    const int CONV_SMEM1  = (64*342 + 64*9*1) * 4;
    const int CONV_SMEM2  = (64*342 + 64*9*2) * 4;

    cudaFuncSetAttribute(pixel_kernel, cudaFuncAttributeMaxDynamicSharedMemorySize, PIX_SMEM);
    cudaFuncSetAttribute(conv3x3_kernel<32, true>,  cudaFuncAttributeMaxDynamicSharedMemorySize, CONV_SMEM32);
    cudaFuncSetAttribute(conv3x3_kernel<1, false>,  cudaFuncAttributeMaxDynamicSharedMemorySize, CONV_SMEM1);
    cudaFuncSetAttribute(conv3x3_kernel<2, false>,  cudaFuncAttributeMaxDynamicSharedMemorySize, CONV_SMEM2);

    stats_kernel<<<QN * RFN * NSS * CNN, 256>>>(corr);

    pixel_kernel<<<dim3(16, NSS, QN), 256, PIX_SMEM>>>(
        corr, scale_w1, scale_b1, scale_w2, scale_b2,
        score_w1, score_b1, score_w2, score_b2);

    maxns_kernel<<<4096, 256>>>();

    // scales head (input xs)
    conv3x3_kernel<32, true><<<dim3(4, 4, QN * 2), 256, CONV_SMEM32>>>(
        xs_p, (const float*)d_in[9], (const float*)d_in[10], t1_p, 64, 2);
    conv3x3_kernel<32, true><<<dim3(4, 4, QN * 2), 256, CONV_SMEM32>>>(
        t1_p, (const float*)d_in[11], (const float*)d_in[12], t2_p, 64, 2);
    conv3x3_kernel<1, false><<<dim3(4, 4, QN), 256, CONV_SMEM1>>>(
        t2_p, (const float*)d_in[13], (const float*)d_in[14], out + OFF_SCALES, 1, 1);

    // offsets head (input xc)
    conv3x3_kernel<32, true><<<dim3(4, 4, QN * 2), 256, CONV_SMEM32>>>(
        xc_p, (const float*)d_in[15], (const float*)d_in[16], t1_p, 64, 2);
    conv3x3_kernel<32, true><<<dim3(4, 4, QN * 2), 256, CONV_SMEM32>>>(
        t1_p, (const float*)d_in[17], (const float*)d_in[18], t2_p, 64, 2);
    conv3x3_kernel<2, false><<<dim3(4, 4, QN), 256, CONV_SMEM2>>>(
        t2_p, (const float*)d_in[19], (const float*)d_in[20], out + OFF_OFFS, 2, 1);

    // scores head (input xc)
    conv3x3_kernel<32, true><<<dim3(4, 4, QN * 2), 256, CONV_SMEM32>>>(
        xc_p, (const float*)d_in[21], (const float*)d_in[22], t1_p, 64, 2);
    conv3x3_kernel<32, true><<<dim3(4, 4, QN * 2), 256, CONV_SMEM32>>>(
        t1_p, (const float*)d_in[23], (const float*)d_in[24], t2_p, 64, 2);
    conv3x3_kernel<1, false><<<dim3(4, 4, QN), 256, CONV_SMEM1>>>(
        t2_p, (const float*)d_in[25], (const float*)d_in[26], out + OFF_SCORES, 1, 1);

    finalize_kernel<<<QN, 256>>>(out);
}

// round 2
// speedup vs baseline: 1.2692x; 1.2692x over previous
#include <cuda_runtime.h>
#include <math.h>

#define QN 4
#define RFN 32
#define NSS 4
#define CNN 18
#define HH 64
#define WW 64
#define HWSZ 4096
#define KNN 4

// Output layout: pos(8), scl(4), scores(4*4096), scales(4*4096), offsets(4*2*4096)
#define OFF_POS 0
#define OFF_SCL 8
#define OFF_SCORES 12
#define OFF_SCALES (12 + 16384)
#define OFF_OFFS (12 + 32768)

// ---------------- f32x2 helpers ----------------
__device__ __forceinline__ unsigned long long pk2(float x) {
    unsigned long long r;
    asm("mov.b64 %0, {%1, %1};" : "=l"(r) : "f"(x));
    return r;
}
__device__ __forceinline__ unsigned long long pk2b(float a, float b) {
    unsigned long long r;
    asm("mov.b64 %0, {%1, %2};" : "=l"(r) : "f"(a), "f"(b));
    return r;
}
__device__ __forceinline__ unsigned long long fma2(unsigned long long a, unsigned long long b,
                                                   unsigned long long c) {
    unsigned long long d;
    asm("fma.rn.f32x2 %0, %1, %2, %3;" : "=l"(d) : "l"(a), "l"(b), "l"(c));
    return d;
}
__device__ __forceinline__ float2 up2(unsigned long long v) {
    float lo, hi;
    asm("mov.b64 {%0, %1}, %2;" : "=f"(lo), "=f"(hi) : "l"(v));
    return make_float2(lo, hi);
}
union F4U2 { float4 f4; unsigned long long u[2]; };

// ---------------- device scratch ----------------
__device__ float g_scale[QN * RFN * NSS * CNN];
__device__ float g_shift[QN * RFN * NSS * CNN];
__device__ float g_ys[QN * NSS * 64 * HWSZ];
__device__ float g_yc[QN * NSS * 64 * HWSZ];
__device__ float g_xs[QN * 64 * HWSZ];
__device__ float g_xc[QN * 64 * HWSZ];
__device__ float g_t1[3 * QN * 64 * HWSZ];
__device__ float g_t2[3 * QN * 64 * HWSZ];

// ---------------- 1) per-channel mean / rstd ----------------
__global__ void stats_kernel(const float* __restrict__ corr) {
    int b = blockIdx.x;
    int tid = threadIdx.x;
    const float* p = corr + (size_t)b * HWSZ;
    double s = 0.0, ss = 0.0;
    for (int i = tid; i < HWSZ; i += 256) {
        float v = p[i];
        s += v;
        ss += (double)v * v;
    }
    for (int o = 16; o > 0; o >>= 1) {
        s += __shfl_down_sync(0xffffffffu, s, o);
        ss += __shfl_down_sync(0xffffffffu, ss, o);
    }
    __shared__ double ws[8], wss[8];
    if ((tid & 31) == 0) { ws[tid >> 5] = s; wss[tid >> 5] = ss; }
    __syncthreads();
    if (tid == 0) {
        double S = 0.0, SS = 0.0;
        for (int i = 0; i < 8; i++) { S += ws[i]; SS += wss[i]; }
        double m = S / (double)HWSZ;
        double var = SS / (double)HWSZ - m * m;
        double rstd = 1.0 / sqrt(var + 1e-5);
        g_scale[b] = (float)rstd;
        g_shift[b] = (float)(-m * rstd);
    }
}

// ---------------- 2) topk + gather + dual MLP per (q,ns,pixel) ----------------
__global__ void pixel_kernel(const float* __restrict__ corr,
                             const float* __restrict__ w1s, const float* __restrict__ b1s,
                             const float* __restrict__ w2s, const float* __restrict__ b2s,
                             const float* __restrict__ w1c, const float* __restrict__ b1c,
                             const float* __restrict__ w2c, const float* __restrict__ b2c) {
    extern __shared__ float sm[];
    float* sSc = sm;                 // 576
    float* sSh = sSc + 576;          // 576
    float* sW1s = sSh + 576;         // 72*64 (transposed: [in][out])
    float* sW2s = sW1s + 4608;       // 64*64 ([o][j])
    float* sW1c = sW2s + 4096;       // 12*64 (transposed)
    float* sW2c = sW1c + 768;        // 64*64
    float* sB1s = sW2c + 4096;       // 64
    float* sB2s = sB1s + 64;
    float* sB1c = sB2s + 64;
    float* sB2c = sB1c + 64;
    float* sLvl = sB2c + 64;         // 256*13

    int tid = threadIdx.x;
    int q = blockIdx.z, ns = blockIdx.y;

    for (int i = tid; i < 576; i += 256) {
        int rf = i / 18, cn = i % 18;
        int ch = ((q * RFN + rf) * NSS + ns) * CNN + cn;
        sSc[i] = g_scale[ch];
        sSh[i] = g_shift[ch];
    }
    for (int i = tid; i < 4608; i += 256) sW1s[i] = w1s[(i & 63) * 72 + (i >> 6)];
    for (int i = tid; i < 4096; i += 256) sW2s[i] = w2s[i];
    for (int i = tid; i < 768;  i += 256) sW1c[i] = w1c[(i & 63) * 12 + (i >> 6)];
    for (int i = tid; i < 4096; i += 256) sW2c[i] = w2c[i];
    if (tid < 64) {
        sB1s[tid] = b1s[tid]; sB2s[tid] = b2s[tid];
        sB1c[tid] = b1c[tid]; sB2c[tid] = b2c[tid];
    }
    __syncthreads();

    int hw = blockIdx.x * 256 + tid;
    int cbase = (q * (RFN * NSS * CNN) + ns * CNN) * HWSZ + hw;

    // ---- phase 1: ref score per rfn + top-4 (stable, strict >) ----
    float v0 = -3.4e38f, v1 = v0, v2 = v0, v3 = v0;
    int i0 = 0, i1 = 0, i2 = 0, i3 = 0;
#pragma unroll 1
    for (int rf = 0; rf < RFN; rf++) {
        const float* cp = corr + cbase + rf * (NSS * CNN) * HWSZ;
        float s = 0.f;
#pragma unroll
        for (int cn = 0; cn < CNN; cn++)
            s += fmaf(cp[cn * HWSZ], sSc[rf * 18 + cn], sSh[rf * 18 + cn]);
        if (s > v0)      { v3=v2;i3=i2; v2=v1;i2=i1; v1=v0;i1=i0; v0=s;i0=rf; }
        else if (s > v1) { v3=v2;i3=i2; v2=v1;i2=i1; v1=s;i1=rf; }
        else if (s > v2) { v3=v2;i3=i2; v2=s;i2=rf; }
        else if (s > v3) { v3=s;i3=rf; }
    }
    unsigned packed = (unsigned)i0 | ((unsigned)i1 << 8) | ((unsigned)i2 << 16) | ((unsigned)i3 << 24);

    // ---- phase 2: gather + 72->64 matvec (scale branch) with f32x2 ----
    unsigned long long h2[32];
#pragma unroll
    for (int j = 0; j < 32; j++) h2[j] = pk2b(sB1s[2*j], sB1s[2*j+1]);
#pragma unroll
    for (int i = 0; i < 12; i++) sLvl[tid * 13 + i] = 0.f;

#pragma unroll 1
    for (int k = 0; k < KNN; k++) {
        int rf = (packed >> (k * 8)) & 255;
        const float* cp = corr + cbase + rf * (NSS * CNN) * HWSZ;
        int sb = rf * 18;
#pragma unroll
        for (int cn = 0; cn < CNN; cn++) {
            float xn = fmaf(cp[cn * HWSZ], sSc[sb + cn], sSh[sb + cn]);
            sLvl[tid * 13 + k * 3 + cn / 6] += xn;
            unsigned long long xx = pk2(xn);
            const float4* wp = (const float4*)&sW1s[(k * 18 + cn) * 64];
#pragma unroll
            for (int jj = 0; jj < 16; jj++) {
                F4U2 w; w.f4 = wp[jj];
                h2[2*jj]   = fma2(xx, w.u[0], h2[2*jj]);
                h2[2*jj+1] = fma2(xx, w.u[1], h2[2*jj+1]);
            }
        }
    }
#pragma unroll
    for (int j = 0; j < 32; j++) {
        float2 v = up2(h2[j]);
        h2[j] = pk2b(fmaxf(v.x, 0.f), fmaxf(v.y, 0.f));
    }

    // ---- phase 3: 64->64 (4 outputs in flight), write scale-branch features ----
    int obase = ((q * NSS + ns) * 64) * HWSZ + hw;
#pragma unroll 1
    for (int o = 0; o < 64; o += 4) {
        unsigned long long a0 = 0, a1 = 0, a2 = 0, a3 = 0;
        const float4* r0 = (const float4*)&sW2s[(o+0) * 64];
        const float4* r1 = (const float4*)&sW2s[(o+1) * 64];
        const float4* r2 = (const float4*)&sW2s[(o+2) * 64];
        const float4* r3 = (const float4*)&sW2s[(o+3) * 64];
#pragma unroll
        for (int jj = 0; jj < 16; jj++) {
            F4U2 w0, w1, w2, w3;
            w0.f4 = r0[jj]; w1.f4 = r1[jj]; w2.f4 = r2[jj]; w3.f4 = r3[jj];
            a0 = fma2(h2[2*jj], w0.u[0], a0); a0 = fma2(h2[2*jj+1], w0.u[1], a0);
            a1 = fma2(h2[2*jj], w1.u[0], a1); a1 = fma2(h2[2*jj+1], w1.u[1], a1);
            a2 = fma2(h2[2*jj], w2.u[0], a2); a2 = fma2(h2[2*jj+1], w2.u[1], a2);
            a3 = fma2(h2[2*jj], w3.u[0], a3); a3 = fma2(h2[2*jj+1], w3.u[1], a3);
        }
        float2 s0 = up2(a0), s1 = up2(a1), s2 = up2(a2), s3 = up2(a3);
        g_ys[obase + (o+0) * HWSZ] = s0.x + s0.y + sB2s[o+0];
        g_ys[obase + (o+1) * HWSZ] = s1.x + s1.y + sB2s[o+1];
        g_ys[obase + (o+2) * HWSZ] = s2.x + s2.y + sB2s[o+2];
        g_ys[obase + (o+3) * HWSZ] = s3.x + s3.y + sB2s[o+3];
    }

    // ---- phase 4: score branch 12->64 ----
#pragma unroll
    for (int j = 0; j < 32; j++) h2[j] = pk2b(sB1c[2*j], sB1c[2*j+1]);
#pragma unroll 1
    for (int i = 0; i < 12; i++) {
        float xv = sLvl[tid * 13 + i] * (1.0f / 6.0f);
        unsigned long long xx = pk2(xv);
        const float4* wp = (const float4*)&sW1c[i * 64];
#pragma unroll
        for (int jj = 0; jj < 16; jj++) {
            F4U2 w; w.f4 = wp[jj];
            h2[2*jj]   = fma2(xx, w.u[0], h2[2*jj]);
            h2[2*jj+1] = fma2(xx, w.u[1], h2[2*jj+1]);
        }
    }
#pragma unroll
    for (int j = 0; j < 32; j++) {
        float2 v = up2(h2[j]);
        h2[j] = pk2b(fmaxf(v.x, 0.f), fmaxf(v.y, 0.f));
    }

    // ---- phase 5: 64->64, write score-branch features ----
#pragma unroll 1
    for (int o = 0; o < 64; o += 4) {
        unsigned long long a0 = 0, a1 = 0, a2 = 0, a3 = 0;
        const float4* r0 = (const float4*)&sW2c[(o+0) * 64];
        const float4* r1 = (const float4*)&sW2c[(o+1) * 64];
        const float4* r2 = (const float4*)&sW2c[(o+2) * 64];
        const float4* r3 = (const float4*)&sW2c[(o+3) * 64];
#pragma unroll
        for (int jj = 0; jj < 16; jj++) {
            F4U2 w0, w1, w2, w3;
            w0.f4 = r0[jj]; w1.f4 = r1[jj]; w2.f4 = r2[jj]; w3.f4 = r3[jj];
            a0 = fma2(h2[2*jj], w0.u[0], a0); a0 = fma2(h2[2*jj+1], w0.u[1], a0);
            a1 = fma2(h2[2*jj], w1.u[0], a1); a1 = fma2(h2[2*jj+1], w1.u[1], a1);
            a2 = fma2(h2[2*jj], w2.u[0], a2); a2 = fma2(h2[2*jj+1], w2.u[1], a2);
            a3 = fma2(h2[2*jj], w3.u[0], a3); a3 = fma2(h2[2*jj+1], w3.u[1], a3);
        }
        float2 s0 = up2(a0), s1 = up2(a1), s2 = up2(a2), s3 = up2(a3);
        g_yc[obase + (o+0) * HWSZ] = s0.x + s0.y + sB2c[o+0];
        g_yc[obase + (o+1) * HWSZ] = s1.x + s1.y + sB2c[o+1];
        g_yc[obase + (o+2) * HWSZ] = s2.x + s2.y + sB2c[o+2];
        g_yc[obase + (o+3) * HWSZ] = s3.x + s3.y + sB2c[o+3];
    }
}

// ---------------- 3) max over ns ----------------
__global__ void maxns_kernel() {
    int idx = blockIdx.x * 256 + threadIdx.x;
    int q = idx >> 18;
    int within = idx & ((1 << 18) - 1);
    int base = (q << 20) + within;
    float a = g_ys[base];
    float b = g_yc[base];
#pragma unroll
    for (int ns = 1; ns < NSS; ns++) {
        a = fmaxf(a, g_ys[base + (ns << 18)]);
        b = fmaxf(b, g_yc[base + (ns << 18)]);
    }
    g_xs[idx] = a;
    g_xc[idx] = b;
}

// ---------------- 4) conv3x3, batched heads ----------------
struct HeadIO {
    const float* in;
    const float* w;
    const float* b;
    float* out;
    int cout;
};

// Middle layers: 64->32 outputs per block, relu, f32x2, 4px x 8out register tile.
// grid (4, 4, 3*QN*2), block 256
__global__ __launch_bounds__(256) void conv_mid_kernel(HeadIO a0, HeadIO a1, HeadIO a2) {
    extern __shared__ float sm[];
    float* tile = sm;                 // 64 * 342 (18 rows x 19 stride)
    float* wsm = sm + 64 * 342;       // [ci][tap][32]

    int tid = threadIdx.x;
    int bz = blockIdx.z;
    int head = bz >> 3;
    int rem = bz & 7;
    int q = rem >> 1;
    int co0 = (rem & 1) * 32;
    HeadIO io = (head == 0) ? a0 : ((head == 1) ? a1 : a2);

    int bx = blockIdx.x * 16, by = blockIdx.y * 16;

    for (int i = tid; i < 64 * 324; i += 256) {
        int ci = i / 324;
        int r = i - ci * 324;
        int yy = r / 18, xx = r - yy * 18;
        int gy = by + yy - 1, gx = bx + xx - 1;
        float v = 0.f;
        if ((unsigned)gy < 64u && (unsigned)gx < 64u)
            v = io.in[(q * 64 + ci) * HWSZ + gy * WW + gx];
        tile[ci * 342 + yy * 19 + xx] = v;
    }
    for (int i = tid; i < 64 * 9 * 32; i += 256) {
        int co = i & 31;
        int tap = (i >> 5) % 9;
        int ci = i / 288;
        wsm[i] = io.w[((co0 + co) * 64 + ci) * 9 + tap];
    }
    __syncthreads();

    int og = tid >> 6;          // 0..3 -> 8 outputs each
    int pg = tid & 63;
    int ty = pg >> 2;           // 0..15
    int tx = (pg & 3) << 2;     // 0,4,8,12

    unsigned long long acc[4][4];
#pragma unroll
    for (int p = 0; p < 4; p++)
#pragma unroll
        for (int c = 0; c < 4; c++) acc[p][c] = 0ull;

#pragma unroll 1
    for (int ci = 0; ci < 64; ci++) {
        const float* t = &tile[ci * 342 + ty * 19 + tx];
        unsigned long long x2[3][6];
#pragma unroll
        for (int dy = 0; dy < 3; dy++)
#pragma unroll
            for (int dx = 0; dx < 6; dx++)
                x2[dy][dx] = pk2(t[dy * 19 + dx]);
        const float4* wp = (const float4*)&wsm[ci * 288 + og * 8];
#pragma unroll
        for (int tap = 0; tap < 9; tap++) {
            F4U2 wa, wb;
            wa.f4 = wp[tap * 8];
            wb.f4 = wp[tap * 8 + 1];
            int dy = tap / 3, dx = tap % 3;
#pragma unroll
            for (int p = 0; p < 4; p++) {
                unsigned long long xv = x2[dy][dx + p];
                acc[p][0] = fma2(xv, wa.u[0], acc[p][0]);
                acc[p][1] = fma2(xv, wa.u[1], acc[p][1]);
                acc[p][2] = fma2(xv, wb.u[0], acc[p][2]);
                acc[p][3] = fma2(xv, wb.u[1], acc[p][3]);
            }
        }
    }

    int ob = (q * 64 + co0 + og * 8) * HWSZ + (by + ty) * WW + bx + tx;
#pragma unroll
    for (int pair = 0; pair < 4; pair++) {
        float2 v0 = up2(acc[0][pair]);
        float2 v1 = up2(acc[1][pair]);
        float2 v2 = up2(acc[2][pair]);
        float2 v3 = up2(acc[3][pair]);
        float blo = io.b[co0 + og * 8 + pair * 2];
        float bhi = io.b[co0 + og * 8 + pair * 2 + 1];
        float4 olo = make_float4(fmaxf(v0.x + blo, 0.f), fmaxf(v1.x + blo, 0.f),
                                 fmaxf(v2.x + blo, 0.f), fmaxf(v3.x + blo, 0.f));
        float4 ohi = make_float4(fmaxf(v0.y + bhi, 0.f), fmaxf(v1.y + bhi, 0.f),
                                 fmaxf(v2.y + bhi, 0.f), fmaxf(v3.y + bhi, 0.f));
        *(float4*)&io.out[ob + (pair * 2) * HWSZ] = olo;
        *(float4*)&io.out[ob + (pair * 2 + 1) * HWSZ] = ohi;
    }
}

// Last layer: up to 2 outputs, no relu. grid (4, 4, 3*QN), block 256 (1 px/thread)
__global__ __launch_bounds__(256) void conv_last_kernel(HeadIO a0, HeadIO a1, HeadIO a2) {
    extern __shared__ float sm[];
    float* tile = sm;                 // 64 * 342
    float* wsm = sm + 64 * 342;       // [ci][tap][2]

    int tid = threadIdx.x;
    int bz = blockIdx.z;
    int head = bz >> 2;
    int q = bz & 3;
    HeadIO io = (head == 0) ? a0 : ((head == 1) ? a1 : a2);
    int Cout = io.cout;

    int bx = blockIdx.x * 16, by = blockIdx.y * 16;

    for (int i = tid; i < 64 * 324; i += 256) {
        int ci = i / 324;
        int r = i - ci * 324;
        int yy = r / 18, xx = r - yy * 18;
        int gy = by + yy - 1, gx = bx + xx - 1;
        float v = 0.f;
        if ((unsigned)gy < 64u && (unsigned)gx < 64u)
            v = io.in[(q * 64 + ci) * HWSZ + gy * WW + gx];
        tile[ci * 342 + yy * 19 + xx] = v;
    }
    for (int i = tid; i < 64 * 9 * 2; i += 256) {
        int co = i & 1;
        int tap = (i >> 1) % 9;
        int ci = i / 18;
        wsm[i] = (co < Cout) ? io.w[(co * 64 + ci) * 9 + tap] : 0.f;
    }
    __syncthreads();

    int tx = tid & 15, ty = tid >> 4;
    float acc0 = 0.f, acc1 = 0.f;

#pragma unroll 1
    for (int ci = 0; ci < 64; ci++) {
        const float* t = &tile[ci * 342 + ty * 19 + tx];
        const float* wp = &wsm[ci * 18];
#pragma unroll
        for (int tap = 0; tap < 9; tap++) {
            float av = t[(tap / 3) * 19 + (tap % 3)];
            acc0 = fmaf(av, wp[tap * 2 + 0], acc0);
            acc1 = fmaf(av, wp[tap * 2 + 1], acc1);
        }
    }

    int gy = by + ty, gx = bx + tx;
    io.out[(q * Cout + 0) * HWSZ + gy * WW + gx] = acc0 + io.b[0];
    if (Cout > 1)
        io.out[(q * Cout + 1) * HWSZ + gy * WW + gx] = acc1 + io.b[1];
}

// ---------------- 5) argmax + pos/scl ----------------
__global__ void finalize_kernel(float* out) {
    __shared__ float sv[256];
    __shared__ int si[256];
    int q = blockIdx.x, tid = threadIdx.x;
    const float* sc = out + OFF_SCORES + q * HWSZ;
    float bv = -3.4e38f;
    int bi = 0;
    for (int i = tid; i < HWSZ; i += 256) {
        float v = sc[i];
        if (v > bv) { bv = v; bi = i; }
    }
    sv[tid] = bv; si[tid] = bi;
    __syncthreads();
    for (int s = 128; s > 0; s >>= 1) {
        if (tid < s) {
            if (sv[tid + s] > sv[tid] || (sv[tid + s] == sv[tid] && si[tid + s] < si[tid])) {
                sv[tid] = sv[tid + s];
                si[tid] = si[tid + s];
            }
        }
        __syncthreads();
    }
    if (tid == 0) {
        int idx = si[0];
        int sy = idx >> 6, sx = idx & 63;
        float offx = out[OFF_OFFS + (q * 2 + 0) * HWSZ + idx];
        float offy = out[OFF_OFFS + (q * 2 + 1) * HWSZ + idx];
        float sclv = out[OFF_SCALES + q * HWSZ + idx];
        out[OFF_POS + q * 2 + 0] = ((float)sx + offx + 0.5f) * 8.0f - 0.5f;
        out[OFF_POS + q * 2 + 1] = ((float)sy + offy + 0.5f) * 8.0f - 0.5f;
        out[OFF_SCL + q] = exp2f(sclv);
    }
}

// ---------------- launch ----------------
extern "C" void kernel_launch(void* const* d_in, const int* in_sizes, int n_in,
                              void* d_out, int out_size) {
    const float* corr = (const float*)d_in[0];
    float* out = (float*)d_out;

    float *xs_p, *xc_p, *t1_p, *t2_p;
    cudaGetSymbolAddress((void**)&xs_p, g_xs);
    cudaGetSymbolAddress((void**)&xc_p, g_xc);
    cudaGetSymbolAddress((void**)&t1_p, g_t1);
    cudaGetSymbolAddress((void**)&t2_p, g_t2);
    const int HSZ = QN * 64 * HWSZ;

    const int PIX_SMEM = (576*2 + 4608 + 4096 + 768 + 4096 + 256 + 256*13) * 4;
    const int MID_SMEM = (64*342 + 64*9*32) * 4;
    const int LAST_SMEM = (64*342 + 64*9*2) * 4;

    cudaFuncSetAttribute(pixel_kernel, cudaFuncAttributeMaxDynamicSharedMemorySize, PIX_SMEM);
    cudaFuncSetAttribute(conv_mid_kernel, cudaFuncAttributeMaxDynamicSharedMemorySize, MID_SMEM);
    cudaFuncSetAttribute(conv_last_kernel, cudaFuncAttributeMaxDynamicSharedMemorySize, LAST_SMEM);

    stats_kernel<<<QN * RFN * NSS * CNN, 256>>>(corr);

    pixel_kernel<<<dim3(16, NSS, QN), 256, PIX_SMEM>>>(
        corr, (const float*)d_in[1], (const float*)d_in[2],
        (const float*)d_in[3], (const float*)d_in[4],
        (const float*)d_in[5], (const float*)d_in[6],
        (const float*)d_in[7], (const float*)d_in[8]);

    maxns_kernel<<<4096, 256>>>();

    // Layer 1 (all heads): scales<-xs, offsets<-xc, scores<-xc
    {
        HeadIO h0 = { xs_p, (const float*)d_in[9],  (const float*)d_in[10], t1_p + 0*HSZ, 64 };
        HeadIO h1 = { xc_p, (const float*)d_in[15], (const float*)d_in[16], t1_p + 1*HSZ, 64 };
        HeadIO h2 = { xc_p, (const float*)d_in[21], (const float*)d_in[22], t1_p + 2*HSZ, 64 };
        conv_mid_kernel<<<dim3(4, 4, 24), 256, MID_SMEM>>>(h0, h1, h2);
    }
    // Layer 2
    {
        HeadIO h0 = { t1_p + 0*HSZ, (const float*)d_in[11], (const float*)d_in[12], t2_p + 0*HSZ, 64 };
        HeadIO h1 = { t1_p + 1*HSZ, (const float*)d_in[17], (const float*)d_in[18], t2_p + 1*HSZ, 64 };
        HeadIO h2 = { t1_p + 2*HSZ, (const float*)d_in[23], (const float*)d_in[24], t2_p + 2*HSZ, 64 };
        conv_mid_kernel<<<dim3(4, 4, 24), 256, MID_SMEM>>>(h0, h1, h2);
    }
    // Layer 3 (final preds)
    {
        HeadIO h0 = { t2_p + 0*HSZ, (const float*)d_in[13], (const float*)d_in[14], out + OFF_SCALES, 1 };
        HeadIO h1 = { t2_p + 1*HSZ, (const float*)d_in[19], (const float*)d_in[20], out + OFF_OFFS, 2 };
        HeadIO h2 = { t2_p + 2*HSZ, (const float*)d_in[25], (const float*)d_in[26], out + OFF_SCORES, 1 };
        conv_last_kernel<<<dim3(4, 4, 12), 256, LAST_SMEM>>>(h0, h1, h2);
    }

    finalize_kernel<<<QN, 256>>>(out);
}